// round 1
// baseline (speedup 1.0000x reference)
#include <cuda_runtime.h>
#include <math.h>
#include <stdint.h>

#define S_LEN 8192
#define LCC   16
#define DW    256
#define DC    64
#define HC    128
#define HH    512
#define CVV   128
#define T_TAGS 64
#define H2    256
#define KIN   384      /* HC + DW */
#define NB    16       /* CTAs per direction in recurrent kernel */
#define RTHREADS 256

/* ------------------- scratch (device globals; no allocation) ------------- */
__device__ float g_Xc[(size_t)LCC * S_LEN * 4 * HC];   /* 268 MB: per-(t,w) input proj + bias */
__device__ int   g_charidx[LCC * S_LEN];
__device__ float g_gates[S_LEN * 4 * HC];
__device__ float g_Hc[S_LEN * HC];
__device__ float g_Cc[S_LEN * HC];
__device__ float g_charfeat[S_LEN * HC];
__device__ float g_embeds[S_LEN * KIN];
__device__ float g_Gf[(size_t)S_LEN * 4 * H2];
__device__ float g_Gb[(size_t)S_LEN * 4 * H2];
__device__ float g_lstm_out[S_LEN * HH];
__device__ float g_logits[S_LEN * T_TAGS];
__device__ float g_hstate[2 * 2 * H2];                 /* [dir][parity][H2] */
__device__ int   g_bar[2];

__device__ __forceinline__ float sigf(float x) { return 1.0f / (1.0f + expf(-x)); }

/* ------------------- init: must run every launch (graph determinism) ----- */
__global__ void init_state() {
    int idx = blockIdx.x * blockDim.x + threadIdx.x;
    if (idx < 2) g_bar[idx] = 0;
    int stride = gridDim.x * blockDim.x;
    for (int i = idx; i < S_LEN * HC; i += stride) {
        g_Hc[i] = 0.0f;
        g_Cc[i] = 0.0f;
    }
}

__global__ void build_charidx(const int* __restrict__ charsets) {
    int idx = blockIdx.x * blockDim.x + threadIdx.x;
    if (idx >= LCC * S_LEN) return;
    int t = idx / S_LEN;
    int w = idx - t * S_LEN;
    g_charidx[idx] = charsets[w * LCC + t];
}

/* ------------------- generic fp32 GEMM: C[M,N] = Arow(m) . B[n,:] + bias --
 * A is [*,K] row-major with row selection:
 *   row = gidx ? gidx[m] : (rev ? M-1-m : m)
 * B is [N,K] row-major. Tiles 64x64x16, 256 threads, 4x4 microtile.      */
__global__ void __launch_bounds__(256) gemm_tn(
    const float* __restrict__ A, int lda,
    const float* __restrict__ B,
    const float* __restrict__ bias,
    float* __restrict__ C, int M, int N, int K,
    const int* __restrict__ gidx, int rev)
{
    __shared__ float4 As4[16 * 16];
    __shared__ float4 Bs4[16 * 16];
    float* As = (float*)As4;
    float* Bs = (float*)Bs4;

    int tid = threadIdx.x;
    int m0 = blockIdx.y * 64, n0 = blockIdx.x * 64;
    int lm = tid >> 2;          /* 0..63 : row/col within tile to load   */
    int kq = tid & 3;           /* which float4 along K                  */

    int mg = m0 + lm;
    int arow = gidx ? gidx[mg] : (rev ? (M - 1 - mg) : mg);
    const float* Ap = A + (size_t)arow * lda;
    const float* Bp = B + (size_t)(n0 + lm) * K;

    int ty = tid >> 4, tx = tid & 15;
    float acc[4][4];
#pragma unroll
    for (int i = 0; i < 4; i++)
#pragma unroll
        for (int j = 0; j < 4; j++) acc[i][j] = 0.0f;

    for (int k0 = 0; k0 < K; k0 += 16) {
        float4 a = *(const float4*)(Ap + k0 + kq * 4);
        float4 b = *(const float4*)(Bp + k0 + kq * 4);
        __syncthreads();
        As[(kq * 4 + 0) * 64 + lm] = a.x;
        As[(kq * 4 + 1) * 64 + lm] = a.y;
        As[(kq * 4 + 2) * 64 + lm] = a.z;
        As[(kq * 4 + 3) * 64 + lm] = a.w;
        Bs[(kq * 4 + 0) * 64 + lm] = b.x;
        Bs[(kq * 4 + 1) * 64 + lm] = b.y;
        Bs[(kq * 4 + 2) * 64 + lm] = b.z;
        Bs[(kq * 4 + 3) * 64 + lm] = b.w;
        __syncthreads();
#pragma unroll
        for (int kk = 0; kk < 16; kk++) {
            float4 av = As4[kk * 16 + ty];
            float4 bv = Bs4[kk * 16 + tx];
            acc[0][0] += av.x * bv.x; acc[0][1] += av.x * bv.y;
            acc[0][2] += av.x * bv.z; acc[0][3] += av.x * bv.w;
            acc[1][0] += av.y * bv.x; acc[1][1] += av.y * bv.y;
            acc[1][2] += av.y * bv.z; acc[1][3] += av.y * bv.w;
            acc[2][0] += av.z * bv.x; acc[2][1] += av.z * bv.y;
            acc[2][2] += av.z * bv.z; acc[2][3] += av.z * bv.w;
            acc[3][0] += av.w * bv.x; acc[3][1] += av.w * bv.y;
            acc[3][2] += av.w * bv.z; acc[3][3] += av.w * bv.w;
        }
    }
#pragma unroll
    for (int i = 0; i < 4; i++) {
        int m = m0 + ty * 4 + i;
        int n = n0 + tx * 4;
        float4 o;
        o.x = acc[i][0]; o.y = acc[i][1]; o.z = acc[i][2]; o.w = acc[i][3];
        if (bias) {
            o.x += bias[n + 0]; o.y += bias[n + 1];
            o.z += bias[n + 2]; o.w += bias[n + 3];
        }
        *(float4*)(C + (size_t)m * N + n) = o;
    }
}

/* ------------------- char LSTM pointwise update --------------------------- */
__global__ void char_update(const int* __restrict__ lengths, int t) {
    int idx = blockIdx.x * blockDim.x + threadIdx.x;
    if (idx >= S_LEN * HC) return;
    int w = idx / HC, u = idx - w * HC;
    const float* xrow = g_Xc + ((size_t)t * S_LEN + w) * (4 * HC);
    const float* grow = g_gates + (size_t)w * (4 * HC);
    float gi = grow[0 * HC + u] + xrow[0 * HC + u];
    float gf = grow[1 * HC + u] + xrow[1 * HC + u];
    float gg = grow[2 * HC + u] + xrow[2 * HC + u];
    float go = grow[3 * HC + u] + xrow[3 * HC + u];
    float c = g_Cc[idx];
    c = sigf(gf) * c + sigf(gi) * tanhf(gg);
    float h = sigf(go) * tanhf(c);
    g_Cc[idx] = c;
    g_Hc[idx] = h;
    if (t == lengths[w] - 1) g_charfeat[idx] = h;
}

/* ------------------- embeds = [charfeat | word_emb[sentence]] ------------- */
__global__ void build_embeds(const int* __restrict__ sentence,
                             const float* __restrict__ word_emb) {
    int idx = blockIdx.x * blockDim.x + threadIdx.x;
    if (idx >= S_LEN * KIN) return;
    int w = idx / KIN, j = idx - w * KIN;
    float v;
    if (j < HC) v = g_charfeat[w * HC + j];
    else        v = word_emb[(size_t)sentence[w] * DW + (j - HC)];
    g_embeds[idx] = v;
}

/* ------------------- persistent bi-directional recurrence -----------------
 * grid = 2*NB CTAs x 256 threads. CTA (d,b) owns h-units [16b,16b+16).
 * thread tid = r_local*4 + seg; r_local = 4*ul + gate_kind.
 * Each thread holds 64 Whh weights in registers (k interleaved by seg so the
 * shared-memory h broadcast is conflict-free). Per-step global spin barrier
 * with monotonic counter; h exchanged through double-buffered global state. */
__global__ void __launch_bounds__(RTHREADS) recurrent_kernel(
    const float* __restrict__ WhhF, const float* __restrict__ WhhB)
{
    int tid = threadIdx.x;
    int d = blockIdx.x / NB;
    int b = blockIdx.x - d * NB;
    const float* Whh = d ? WhhB : WhhF;
    const float* G = d ? g_Gb : g_Gf;

    int r_local = tid >> 2;       /* 0..63  */
    int seg = tid & 3;            /* 0..3   */
    int ul = r_local >> 2;        /* 0..15  */
    int gk = r_local & 3;         /* i,f,g,o */
    int u = b * 16 + ul;
    int row_global = gk * H2 + u;

    float4 w4[16];
#pragma unroll
    for (int j = 0; j < 16; j++)
        w4[j] = *(const float4*)(Whh + (size_t)row_global * H2 + (j * 4 + seg) * 4);

    __shared__ float s_h[H2];
    __shared__ float s_gates[64];
    s_h[tid] = 0.0f;              /* RTHREADS == H2 */
    float c = 0.0f;

    volatile float* hst = (volatile float*)(g_hstate + d * 2 * H2);
    volatile int* bar = (volatile int*)(g_bar + d);
    __syncthreads();

    for (int t = 0; t < S_LEN; t++) {
        float gin = 0.0f;
        if (seg == 0) gin = G[(size_t)t * (4 * H2) + row_global];

        const float4* sh4 = (const float4*)s_h;
        float acc = 0.0f;
#pragma unroll
        for (int j = 0; j < 16; j++) {
            float4 hv = sh4[j * 4 + seg];
            acc += w4[j].x * hv.x + w4[j].y * hv.y
                 + w4[j].z * hv.z + w4[j].w * hv.w;
        }
        acc += __shfl_xor_sync(0xffffffffu, acc, 1);
        acc += __shfl_xor_sync(0xffffffffu, acc, 2);
        if (seg == 0) s_gates[r_local] = acc + gin;
        __syncthreads();

        if (tid < 16) {
            float gi = s_gates[tid * 4 + 0];
            float gf = s_gates[tid * 4 + 1];
            float gg = s_gates[tid * 4 + 2];
            float go = s_gates[tid * 4 + 3];
            c = sigf(gf) * c + sigf(gi) * tanhf(gg);
            float h = sigf(go) * tanhf(c);
            int uu = b * 16 + tid;
            hst[(t & 1) * H2 + uu] = h;
            int outrow = d ? (S_LEN - 1 - t) : t;
            g_lstm_out[(size_t)outrow * HH + d * H2 + uu] = h;
        }
        __threadfence();
        __syncthreads();
        if (tid == 0) {
            atomicAdd((int*)bar, 1);
            while (*bar < NB * (t + 1)) { }
        }
        __syncthreads();
        s_h[tid] = hst[(t & 1) * H2 + tid];
        __syncthreads();
    }
}

/* ------------------- log_softmax over 64 tags (one warp per word) --------- */
__global__ void logsoftmax_kernel(float* __restrict__ out) {
    int gt = blockIdx.x * blockDim.x + threadIdx.x;
    int warp = gt >> 5;
    int lane = gt & 31;
    if (warp >= S_LEN) return;
    const float* l = g_logits + (size_t)warp * T_TAGS;
    float a = l[lane], b = l[lane + 32];
    float m = fmaxf(a, b);
#pragma unroll
    for (int o = 16; o > 0; o >>= 1) m = fmaxf(m, __shfl_xor_sync(0xffffffffu, m, o));
    float s = expf(a - m) + expf(b - m);
#pragma unroll
    for (int o = 16; o > 0; o >>= 1) s += __shfl_xor_sync(0xffffffffu, s, o);
    float lse = m + logf(s);
    out[(size_t)warp * T_TAGS + lane] = a - lse;
    out[(size_t)warp * T_TAGS + lane + 32] = b - lse;
}

/* ------------------- launcher --------------------------------------------- */
extern "C" void kernel_launch(void* const* d_in, const int* in_sizes, int n_in,
                              void* d_out, int out_size) {
    const int*   sentence  = (const int*)d_in[0];
    const int*   charsets  = (const int*)d_in[1];
    const int*   lengths   = (const int*)d_in[2];
    const float* word_emb  = (const float*)d_in[3];
    const float* char_emb  = (const float*)d_in[4];
    const float* cWih      = (const float*)d_in[5];
    const float* cWhh      = (const float*)d_in[6];
    const float* cb        = (const float*)d_in[7];
    const float* fWih      = (const float*)d_in[8];
    const float* fWhh      = (const float*)d_in[9];
    const float* fb        = (const float*)d_in[10];
    const float* bWih      = (const float*)d_in[11];
    const float* bWhh      = (const float*)d_in[12];
    const float* bb        = (const float*)d_in[13];
    const float* outW      = (const float*)d_in[14];
    const float* outb      = (const float*)d_in[15];
    float* out = (float*)d_out;

    void *pXc, *pIdx, *pGates, *pHc, *pEmb, *pGf, *pGb, *pLout, *pLog;
    cudaGetSymbolAddress(&pXc, g_Xc);
    cudaGetSymbolAddress(&pIdx, g_charidx);
    cudaGetSymbolAddress(&pGates, g_gates);
    cudaGetSymbolAddress(&pHc, g_Hc);
    cudaGetSymbolAddress(&pEmb, g_embeds);
    cudaGetSymbolAddress(&pGf, g_Gf);
    cudaGetSymbolAddress(&pGb, g_Gb);
    cudaGetSymbolAddress(&pLout, g_lstm_out);
    cudaGetSymbolAddress(&pLog, g_logits);

    /* reset per-launch state (graph-replay determinism) */
    init_state<<<2048, 256>>>();

    /* char LSTM input projection for all (t,w): gather + GEMM */
    build_charidx<<<(LCC * S_LEN + 255) / 256, 256>>>(charsets);
    gemm_tn<<<dim3(4 * HC / 64, LCC * S_LEN / 64), 256>>>(
        char_emb, DC, cWih, cb, (float*)pXc,
        LCC * S_LEN, 4 * HC, DC, (const int*)pIdx, 0);

    /* char LSTM: 16 time steps, batched over S */
    for (int t = 0; t < LCC; t++) {
        gemm_tn<<<dim3(4 * HC / 64, S_LEN / 64), 256>>>(
            (const float*)pHc, HC, cWhh, nullptr, (float*)pGates,
            S_LEN, 4 * HC, HC, nullptr, 0);
        char_update<<<S_LEN * HC / 256, 256>>>(lengths, t);
    }

    /* embeds + main input projections */
    build_embeds<<<S_LEN * KIN / 256, 256>>>(sentence, word_emb);
    gemm_tn<<<dim3(4 * H2 / 64, S_LEN / 64), 256>>>(
        (const float*)pEmb, KIN, fWih, fb, (float*)pGf,
        S_LEN, 4 * H2, KIN, nullptr, 0);
    gemm_tn<<<dim3(4 * H2 / 64, S_LEN / 64), 256>>>(
        (const float*)pEmb, KIN, bWih, bb, (float*)pGb,
        S_LEN, 4 * H2, KIN, nullptr, 1);

    /* sequential bidirectional recurrence (persistent kernel) */
    recurrent_kernel<<<2 * NB, RTHREADS>>>(fWhh, bWhh);

    /* output projection + log_softmax */
    gemm_tn<<<dim3(T_TAGS / 64, S_LEN / 64), 256>>>(
        (const float*)pLout, HH, outW, outb, (float*)pLog,
        S_LEN, T_TAGS, HH, nullptr, 0);
    logsoftmax_kernel<<<(S_LEN * 32 + 255) / 256, 256>>>(out);
}